// round 1
// baseline (speedup 1.0000x reference)
#include <cuda_runtime.h>
#include <math.h>
#include <stdint.h>

#define NH   16
#define DHD  64
#define NB   4
#define LQ   1024
#define LK   2048
#define DM   1024
#define MAXPOS 2048

// ---------------- static device scratch (no allocations allowed) ----------------
__device__ float g_Q[(size_t)NB*NH*LQ*DHD];   // [B,H,Lq,64]  16.8 MB
__device__ float g_K[(size_t)NB*NH*LK*DHD];   // [B,H,Lk,64]  33.6 MB
__device__ float g_V[(size_t)NB*NH*LK*DHD];   // [B,H,Lk,64]  33.6 MB

// =================================================================================
// Projection GEMM:  out[b,h,l,dh] = sum_k X[b*L+l, k] * W[h*64+dh, k] + bias[...]
// Tile 128x128, BK=16, 256 threads, 8x8 microtile, double-buffered smem.
// =================================================================================
__global__ __launch_bounds__(256, 2)
void proj_kernel(const float* __restrict__ X, const float* __restrict__ W,
                 const float* __restrict__ bias, float* __restrict__ out, int L)
{
    __shared__ __align__(16) float Xs[2][16][132];
    __shared__ __align__(16) float Ws[2][16][132];

    const int t  = threadIdx.x;
    const int tx = t & 15;
    const int ty = t >> 4;
    const int n0 = blockIdx.x * 128;
    const int m0 = blockIdx.y * 128;

    // each thread loads 2 float4 per tile per matrix (128 rows x 16 cols)
    const int g0   = t * 2;
    const int row0 = g0 >> 2,       c40 = g0 & 3;
    const int row1 = (g0 + 1) >> 2, c41 = (g0 + 1) & 3;

    float4 xr0, xr1, wr0, wr1;

    // prefetch k-tile 0
    xr0 = *(const float4*)(X + (size_t)(n0 + row0) * DM + c40 * 4);
    xr1 = *(const float4*)(X + (size_t)(n0 + row1) * DM + c41 * 4);
    wr0 = *(const float4*)(W + (size_t)(m0 + row0) * DM + c40 * 4);
    wr1 = *(const float4*)(W + (size_t)(m0 + row1) * DM + c41 * 4);

    float acc[8][8];
#pragma unroll
    for (int i = 0; i < 8; i++)
#pragma unroll
        for (int j = 0; j < 8; j++) acc[i][j] = 0.0f;

    // store tile 0 (transposed: Xs[k][row])
    Xs[0][c40*4+0][row0] = xr0.x; Xs[0][c40*4+1][row0] = xr0.y;
    Xs[0][c40*4+2][row0] = xr0.z; Xs[0][c40*4+3][row0] = xr0.w;
    Xs[0][c41*4+0][row1] = xr1.x; Xs[0][c41*4+1][row1] = xr1.y;
    Xs[0][c41*4+2][row1] = xr1.z; Xs[0][c41*4+3][row1] = xr1.w;
    Ws[0][c40*4+0][row0] = wr0.x; Ws[0][c40*4+1][row0] = wr0.y;
    Ws[0][c40*4+2][row0] = wr0.z; Ws[0][c40*4+3][row0] = wr0.w;
    Ws[0][c41*4+0][row1] = wr1.x; Ws[0][c41*4+1][row1] = wr1.y;
    Ws[0][c41*4+2][row1] = wr1.z; Ws[0][c41*4+3][row1] = wr1.w;
    __syncthreads();

    const int NK = DM / 16;
    for (int kt = 0; kt < NK; kt++) {
        const int buf = kt & 1;
        if (kt + 1 < NK) {
            const int k0 = (kt + 1) * 16;
            xr0 = *(const float4*)(X + (size_t)(n0 + row0) * DM + k0 + c40 * 4);
            xr1 = *(const float4*)(X + (size_t)(n0 + row1) * DM + k0 + c41 * 4);
            wr0 = *(const float4*)(W + (size_t)(m0 + row0) * DM + k0 + c40 * 4);
            wr1 = *(const float4*)(W + (size_t)(m0 + row1) * DM + k0 + c41 * 4);
        }
#pragma unroll
        for (int kk = 0; kk < 16; kk++) {
            float a[8], b[8];
            float4 a0 = *(const float4*)&Xs[buf][kk][ty * 8];
            float4 a1 = *(const float4*)&Xs[buf][kk][ty * 8 + 4];
            float4 b0 = *(const float4*)&Ws[buf][kk][tx * 8];
            float4 b1 = *(const float4*)&Ws[buf][kk][tx * 8 + 4];
            a[0]=a0.x; a[1]=a0.y; a[2]=a0.z; a[3]=a0.w;
            a[4]=a1.x; a[5]=a1.y; a[6]=a1.z; a[7]=a1.w;
            b[0]=b0.x; b[1]=b0.y; b[2]=b0.z; b[3]=b0.w;
            b[4]=b1.x; b[5]=b1.y; b[6]=b1.z; b[7]=b1.w;
#pragma unroll
            for (int i = 0; i < 8; i++)
#pragma unroll
                for (int j = 0; j < 8; j++)
                    acc[i][j] = fmaf(a[i], b[j], acc[i][j]);
        }
        if (kt + 1 < NK) {
            __syncthreads();
            const int nb = buf ^ 1;
            Xs[nb][c40*4+0][row0] = xr0.x; Xs[nb][c40*4+1][row0] = xr0.y;
            Xs[nb][c40*4+2][row0] = xr0.z; Xs[nb][c40*4+3][row0] = xr0.w;
            Xs[nb][c41*4+0][row1] = xr1.x; Xs[nb][c41*4+1][row1] = xr1.y;
            Xs[nb][c41*4+2][row1] = xr1.z; Xs[nb][c41*4+3][row1] = xr1.w;
            Ws[nb][c40*4+0][row0] = wr0.x; Ws[nb][c40*4+1][row0] = wr0.y;
            Ws[nb][c40*4+2][row0] = wr0.z; Ws[nb][c40*4+3][row0] = wr0.w;
            Ws[nb][c41*4+0][row1] = wr1.x; Ws[nb][c41*4+1][row1] = wr1.y;
            Ws[nb][c41*4+2][row1] = wr1.z; Ws[nb][c41*4+3][row1] = wr1.w;
            __syncthreads();
        }
    }

    // epilogue: add bias, scatter into [B,H,L,64] layout
#pragma unroll
    for (int i = 0; i < 8; i++) {
        const int n    = n0 + ty * 8 + i;
        const int bidx = n / L;
        const int l    = n - bidx * L;
#pragma unroll
        for (int jj = 0; jj < 2; jj++) {
            const int m  = m0 + tx * 8 + jj * 4;
            const int hh = m >> 6;
            const int dh = m & 63;
            float4 v;
            v.x = acc[i][jj*4+0] + __ldg(&bias[m+0]);
            v.y = acc[i][jj*4+1] + __ldg(&bias[m+1]);
            v.z = acc[i][jj*4+2] + __ldg(&bias[m+2]);
            v.w = acc[i][jj*4+3] + __ldg(&bias[m+3]);
            *(float4*)(out + ((size_t)(bidx * NH + hh) * L + l) * DHD + dh) = v;
        }
    }
}

// =================================================================================
// Fused attention with relative_key_query position scores (flash-style).
// Block = (q-tile of 64) x (head) x (batch), 256 threads (16x16), 4x4 microtile
// with stride-16 element ownership (bank-conflict-free smem access).
// s[l,r] = q[l]·k[r] + (q[l]+k[r])·e[l-r]   (127-row E window per 64x64 tile)
// =================================================================================
#define SMEM_FLOATS (4*64*65 + 127*65 + 64)
#define SMEM_BYTES  (SMEM_FLOATS * 4)

__global__ __launch_bounds__(256, 2)
void attn_kernel(const float* __restrict__ mask, const float* __restrict__ dist_emb,
                 float* __restrict__ out)
{
    extern __shared__ float sm[];
    float* Qs = sm;                 // [64][65]
    float* Ks = Qs + 64 * 65;       // [64][65]
    float* Vs = Ks + 64 * 65;       // [64][65]
    float* Ps = Vs + 64 * 65;       // [64][65]
    float* Es = Ps + 64 * 65;       // [127][65]
    float* Ms = Es + 127 * 65;      // [64]

    const int t  = threadIdx.x;
    const int tx = t & 15;
    const int ty = t >> 4;
    const int qt = blockIdx.x;
    const int h  = blockIdx.y;
    const int b  = blockIdx.z;
    const int l0 = qt * 64;

    const float* Qg  = g_Q + ((size_t)(b * NH + h) * LQ + l0) * DHD;
    const float* Kg0 = g_K + (size_t)(b * NH + h) * LK * DHD;
    const float* Vg0 = g_V + (size_t)(b * NH + h) * LK * DHD;

    // load Q tile (stride-65 padded)
    for (int g = t; g < 64 * 16; g += 256) {
        const int row = g >> 4, c4 = g & 15;
        float4 v = *(const float4*)(Qg + (size_t)row * 64 + c4 * 4);
        float* p = &Qs[row * 65 + c4 * 4];
        p[0] = v.x; p[1] = v.y; p[2] = v.z; p[3] = v.w;
    }

    float O[4][4];
    float mrow[4], lsum[4];
#pragma unroll
    for (int i = 0; i < 4; i++) {
        mrow[i] = -INFINITY; lsum[i] = 0.0f;
#pragma unroll
        for (int j = 0; j < 4; j++) O[i][j] = 0.0f;
    }

    // precomputed smem bases
    int qb[4], kb[4], eb[7];
#pragma unroll
    for (int i = 0; i < 4; i++) qb[i] = (ty + 16 * i) * 65;
#pragma unroll
    for (int j = 0; j < 4; j++) kb[j] = (tx + 16 * j) * 65;
    const int dl0 = ty - tx + 15;
#pragma unroll
    for (int m = 0; m < 7; m++) eb[m] = (dl0 + 16 * m) * 65;

    for (int kt = 0; kt < LK / 64; kt++) {
        const int r0 = kt * 64;
        __syncthreads();  // protect smem from previous iteration's readers

        // load K, V tiles
        for (int g = t; g < 64 * 16; g += 256) {
            const int row = g >> 4, c4 = g & 15;
            float4 kv = *(const float4*)(Kg0 + (size_t)(r0 + row) * 64 + c4 * 4);
            float* pk = &Ks[row * 65 + c4 * 4];
            pk[0] = kv.x; pk[1] = kv.y; pk[2] = kv.z; pk[3] = kv.w;
            float4 vv = *(const float4*)(Vg0 + (size_t)(r0 + row) * 64 + c4 * 4);
            float* pv = &Vs[row * 65 + c4 * 4];
            pv[0] = vv.x; pv[1] = vv.y; pv[2] = vv.z; pv[3] = vv.w;
        }
        // load E window: global emb row = idx_base + dl, dl in [0,126]
        const int idx_base = l0 - r0 + (MAXPOS - 64);  // l0 - r0 - 63 + 2047
        for (int g = t; g < 127 * 16; g += 256) {
            const int row = g >> 4, c4 = g & 15;
            float4 ev = *(const float4*)(dist_emb + (size_t)(idx_base + row) * 64 + c4 * 4);
            float* pe = &Es[row * 65 + c4 * 4];
            pe[0] = ev.x; pe[1] = ev.y; pe[2] = ev.z; pe[3] = ev.w;
        }
        if (t < 64) Ms[t] = mask[(size_t)b * LK + r0 + t];
        __syncthreads();

        // ---- scores: s[i][j] over rows (ty+16i), cols (tx+16j) ----
        float s[4][4];
#pragma unroll
        for (int i = 0; i < 4; i++)
#pragma unroll
            for (int j = 0; j < 4; j++) s[i][j] = 0.0f;

#pragma unroll 4
        for (int d = 0; d < 64; d++) {
            float a[4], kv[4], e[7];
#pragma unroll
            for (int i = 0; i < 4; i++) a[i]  = Qs[qb[i] + d];
#pragma unroll
            for (int j = 0; j < 4; j++) kv[j] = Ks[kb[j] + d];
#pragma unroll
            for (int m = 0; m < 7; m++) e[m]  = Es[eb[m] + d];
#pragma unroll
            for (int i = 0; i < 4; i++)
#pragma unroll
                for (int j = 0; j < 4; j++) {
                    s[i][j] = fmaf(a[i], kv[j], s[i][j]);
                    s[i][j] = fmaf(a[i] + kv[j], e[i - j + 3], s[i][j]);
                }
        }

        // ---- online softmax update ----
#pragma unroll
        for (int i = 0; i < 4; i++) {
            float sv[4];
            float rmax = -INFINITY;
#pragma unroll
            for (int j = 0; j < 4; j++) {
                sv[j] = s[i][j] * 0.125f + Ms[tx + 16 * j];
                rmax  = fmaxf(rmax, sv[j]);
            }
#pragma unroll
            for (int off = 1; off < 16; off <<= 1)
                rmax = fmaxf(rmax, __shfl_xor_sync(0xffffffffu, rmax, off));
            const float mnew = fmaxf(mrow[i], rmax);
            const float corr = __expf(mrow[i] - mnew);
            float rs = 0.0f;
#pragma unroll
            for (int j = 0; j < 4; j++) {
                const float p = __expf(sv[j] - mnew);
                s[i][j] = p;
                rs += p;
            }
#pragma unroll
            for (int off = 1; off < 16; off <<= 1)
                rs += __shfl_xor_sync(0xffffffffu, rs, off);
            lsum[i] = lsum[i] * corr + rs;
#pragma unroll
            for (int j = 0; j < 4; j++) O[i][j] *= corr;
            mrow[i] = mnew;
        }

        // stage P, then PV GEMM
#pragma unroll
        for (int i = 0; i < 4; i++)
#pragma unroll
            for (int j = 0; j < 4; j++)
                Ps[qb[i] + tx + 16 * j] = s[i][j];
        __syncthreads();

#pragma unroll 4
        for (int r = 0; r < 64; r++) {
            float pr[4], vv[4];
#pragma unroll
            for (int i = 0; i < 4; i++) pr[i] = Ps[qb[i] + r];
#pragma unroll
            for (int j = 0; j < 4; j++) vv[j] = Vs[r * 65 + tx + 16 * j];
#pragma unroll
            for (int i = 0; i < 4; i++)
#pragma unroll
                for (int j = 0; j < 4; j++)
                    O[i][j] = fmaf(pr[i], vv[j], O[i][j]);
        }
    }

    // ---- write output [B, Lq, H*64] ----
#pragma unroll
    for (int i = 0; i < 4; i++) {
        const int l = l0 + ty + 16 * i;
        const float inv = 1.0f / lsum[i];
        float* op = out + ((size_t)b * LQ + l) * DM + h * 64;
#pragma unroll
        for (int j = 0; j < 4; j++)
            op[tx + 16 * j] = O[i][j] * inv;
    }
}

// =================================================================================
extern "C" void kernel_launch(void* const* d_in, const int* in_sizes, int n_in,
                              void* d_out, int out_size)
{
    const float* hidden   = (const float*)d_in[0];  // [4,2048,1024]
    const float* q_hidden = (const float*)d_in[1];  // [4,1024,1024]
    const float* mask     = (const float*)d_in[2];  // [4,1,1,2048]
    const float* Wq       = (const float*)d_in[3];
    const float* bq       = (const float*)d_in[4];
    const float* Wk       = (const float*)d_in[5];
    const float* bk       = (const float*)d_in[6];
    const float* Wv       = (const float*)d_in[7];
    const float* bv       = (const float*)d_in[8];
    const float* dist     = (const float*)d_in[9];  // [4095,64]
    float* out = (float*)d_out;

    float *Qp, *Kp, *Vp;
    cudaGetSymbolAddress((void**)&Qp, g_Q);
    cudaGetSymbolAddress((void**)&Kp, g_K);
    cudaGetSymbolAddress((void**)&Vp, g_V);

    // attention kernel needs ~100 KB dynamic smem (attribute persists; the
    // correctness call before capture sets it)
    cudaFuncSetAttribute(attn_kernel, cudaFuncAttributeMaxDynamicSharedMemorySize,
                         SMEM_BYTES);

    dim3 gq(LQ * NB / 128, DM / 128);   // 32 x 8
    dim3 gk(LK * NB / 128, DM / 128);   // 64 x 8
    proj_kernel<<<gq, 256>>>(q_hidden, Wq, bq, Qp, LQ);
    proj_kernel<<<gk, 256>>>(hidden,   Wk, bk, Kp, LK);
    proj_kernel<<<gk, 256>>>(hidden,   Wv, bv, Vp, LK);

    dim3 ga(LQ / 64, NH, NB);           // 16 x 16 x 4
    attn_kernel<<<ga, 256, SMEM_BYTES>>>(mask, dist, out);
}

// round 3
// speedup vs baseline: 1.2269x; 1.2269x over previous
#include <cuda_runtime.h>
#include <cuda_bf16.h>
#include <math.h>
#include <stdint.h>

#define NH   16
#define DHD  64
#define NB   4
#define LQ   1024
#define LK   2048
#define DM   1024
#define MAXPOS 2048

// ---------------- static device scratch (no allocations allowed) ----------------
__device__ float g_Q[(size_t)NB*NH*LQ*DHD];   // [B,H,Lq,64]
__device__ float g_K[(size_t)NB*NH*LK*DHD];   // [B,H,Lk,64]
__device__ float g_V[(size_t)NB*NH*LK*DHD];   // [B,H,Lk,64]

// bf16 split buffers
__device__ __nv_bfloat16 g_Xqh[(size_t)NB*LQ*DM];
__device__ __nv_bfloat16 g_Xql[(size_t)NB*LQ*DM];
__device__ __nv_bfloat16 g_Xkh[(size_t)NB*LK*DM];
__device__ __nv_bfloat16 g_Xkl[(size_t)NB*LK*DM];
__device__ __nv_bfloat16 g_Wh[3][(size_t)DM*DM];
__device__ __nv_bfloat16 g_Wl[3][(size_t)DM*DM];

// ============================ helpers ============================
__device__ __forceinline__ uint32_t smem_u32(const void* p) {
    uint32_t a;
    asm("{ .reg .u64 t; cvta.to.shared.u64 t, %1; cvt.u32.u64 %0, t; }"
        : "=r"(a) : "l"(p));
    return a;
}

__device__ __forceinline__ void cp_async16(uint32_t saddr, const void* gaddr) {
    asm volatile("cp.async.cg.shared.global [%0], [%1], 16;" ::
                 "r"(saddr), "l"(gaddr));
}
__device__ __forceinline__ void cp_commit() {
    asm volatile("cp.async.commit_group;");
}
template <int N>
__device__ __forceinline__ void cp_wait() {
    asm volatile("cp.async.wait_group %0;" :: "n"(N));
}

// mma.sync m16n8k16 bf16 -> f32 (fallback HMMA path, legal in compute_103 PTX)
__device__ __forceinline__ void mma_bf16(float* c, const uint32_t* a, const uint32_t* b) {
    asm volatile(
        "mma.sync.aligned.m16n8k16.row.col.f32.bf16.bf16.f32 "
        "{%0,%1,%2,%3}, {%4,%5,%6,%7}, {%8,%9}, {%0,%1,%2,%3};"
        : "+f"(c[0]), "+f"(c[1]), "+f"(c[2]), "+f"(c[3])
        : "r"(a[0]), "r"(a[1]), "r"(a[2]), "r"(a[3]),
          "r"(b[0]), "r"(b[1]));
}

// =================================================================================
// fp32 -> bf16 (hi, lo) split, vectorized by 4
// =================================================================================
__global__ void split_kernel(const float* __restrict__ x,
                             __nv_bfloat16* __restrict__ hi,
                             __nv_bfloat16* __restrict__ lo, int n4)
{
    int i = blockIdx.x * blockDim.x + threadIdx.x;
    if (i >= n4) return;
    float4 v = ((const float4*)x)[i];
    __nv_bfloat16 h0 = __float2bfloat16(v.x);
    __nv_bfloat16 h1 = __float2bfloat16(v.y);
    __nv_bfloat16 h2 = __float2bfloat16(v.z);
    __nv_bfloat16 h3 = __float2bfloat16(v.w);
    __nv_bfloat16 l0 = __float2bfloat16(v.x - __bfloat162float(h0));
    __nv_bfloat16 l1 = __float2bfloat16(v.y - __bfloat162float(h1));
    __nv_bfloat16 l2 = __float2bfloat16(v.z - __bfloat162float(h2));
    __nv_bfloat16 l3 = __float2bfloat16(v.w - __bfloat162float(h3));
    ((__nv_bfloat162*)hi)[2*i]   = __nv_bfloat162(h0, h1);
    ((__nv_bfloat162*)hi)[2*i+1] = __nv_bfloat162(h2, h3);
    ((__nv_bfloat162*)lo)[2*i]   = __nv_bfloat162(l0, l1);
    ((__nv_bfloat162*)lo)[2*i+1] = __nv_bfloat162(l2, l3);
}

// =================================================================================
// Projection GEMM via mma.sync bf16 split:
//   out[m,n] = sum_k X[m,k]*W[n,k] + bias[n],  D = Ah*Bh + Ah*Bl + Al*Bh
// Block 128x128x32, 8 warps (warp tile 32x64), cp.async double buffer.
// smem row stride 40 bf16 -> conflict-free LDS fragment loads.
// Output scattered to [B,H,L,64].
// =================================================================================
#define BK      32
#define KS_STR  40                         // bf16 units per smem row
#define TILE_BF (128 * KS_STR)             // 5120 bf16 = 10240 B per tile
#define STAGE_BF (4 * TILE_BF)             // Ah, Al, Bh, Bl
#define PROJ_SMEM_BYTES (2 * STAGE_BF * 2) // 81920 B

__global__ __launch_bounds__(256, 1)
void proj_tc(const __nv_bfloat16* __restrict__ Ah_g, const __nv_bfloat16* __restrict__ Al_g,
             const __nv_bfloat16* __restrict__ Bh_g, const __nv_bfloat16* __restrict__ Bl_g,
             const float* __restrict__ bias, float* __restrict__ out, int L)
{
    extern __shared__ __nv_bfloat16 smem[];
    const uint32_t smem_b = smem_u32(smem);

    const int t    = threadIdx.x;
    const int wid  = t >> 5;
    const int lane = t & 31;
    const int g    = lane >> 2;      // group 0..7
    const int t4   = lane & 3;
    const int wm0  = (wid & 3) * 32; // warp row offset in block tile
    const int wn0  = (wid >> 2) * 64;
    const int m0   = blockIdx.x * 128;
    const int n0   = blockIdx.y * 128;

    // global load mapping: 2 uint4 per thread per tile
    const int c0   = t * 2;
    const int row0 = c0 >> 2,       seg0 = c0 & 3;
    const int row1 = (c0 + 1) >> 2, seg1 = (c0 + 1) & 3;

    const int NS = DM / BK;

    auto load_stage = [&](int kc) {
        const int buf = kc & 1;
        const int k0  = kc * BK;
        const uint32_t sb = smem_b + (uint32_t)buf * STAGE_BF * 2;
        const uint32_t so0 = (uint32_t)(row0 * KS_STR + seg0 * 8) * 2;
        const uint32_t so1 = (uint32_t)(row1 * KS_STR + seg1 * 8) * 2;
        const size_t ga0 = (size_t)(m0 + row0) * DM + k0 + seg0 * 8;
        const size_t ga1 = (size_t)(m0 + row1) * DM + k0 + seg1 * 8;
        const size_t gb0 = (size_t)(n0 + row0) * DM + k0 + seg0 * 8;
        const size_t gb1 = (size_t)(n0 + row1) * DM + k0 + seg1 * 8;
        cp_async16(sb + 0 * TILE_BF * 2 + so0, Ah_g + ga0);
        cp_async16(sb + 0 * TILE_BF * 2 + so1, Ah_g + ga1);
        cp_async16(sb + 1 * TILE_BF * 2 + so0, Al_g + ga0);
        cp_async16(sb + 1 * TILE_BF * 2 + so1, Al_g + ga1);
        cp_async16(sb + 2 * TILE_BF * 2 + so0, Bh_g + gb0);
        cp_async16(sb + 2 * TILE_BF * 2 + so1, Bh_g + gb1);
        cp_async16(sb + 3 * TILE_BF * 2 + so0, Bl_g + gb0);
        cp_async16(sb + 3 * TILE_BF * 2 + so1, Bl_g + gb1);
        cp_commit();
    };

    float acc[2][8][4];
#pragma unroll
    for (int i = 0; i < 2; i++)
#pragma unroll
        for (int j = 0; j < 8; j++)
#pragma unroll
            for (int q = 0; q < 4; q++) acc[i][j][q] = 0.0f;

    load_stage(0);

    for (int kc = 0; kc < NS; kc++) {
        if (kc + 1 < NS) { load_stage(kc + 1); cp_wait<1>(); }
        else             { cp_wait<0>(); }
        __syncthreads();

        const __nv_bfloat16* sAh = smem + (size_t)(kc & 1) * STAGE_BF;
        const __nv_bfloat16* sAl = sAh + TILE_BF;
        const __nv_bfloat16* sBh = sAl + TILE_BF;
        const __nv_bfloat16* sBl = sBh + TILE_BF;

#pragma unroll
        for (int ks = 0; ks < BK; ks += 16) {
            uint32_t aH[2][4], aL[2][4], bH[8][2], bL[8][2];
            const int kk = ks + t4 * 2;
#pragma unroll
            for (int i = 0; i < 2; i++) {
                const int r = wm0 + i * 16 + g;
                aH[i][0] = *(const uint32_t*)&sAh[r * KS_STR + kk];
                aH[i][1] = *(const uint32_t*)&sAh[(r + 8) * KS_STR + kk];
                aH[i][2] = *(const uint32_t*)&sAh[r * KS_STR + kk + 8];
                aH[i][3] = *(const uint32_t*)&sAh[(r + 8) * KS_STR + kk + 8];
                aL[i][0] = *(const uint32_t*)&sAl[r * KS_STR + kk];
                aL[i][1] = *(const uint32_t*)&sAl[(r + 8) * KS_STR + kk];
                aL[i][2] = *(const uint32_t*)&sAl[r * KS_STR + kk + 8];
                aL[i][3] = *(const uint32_t*)&sAl[(r + 8) * KS_STR + kk + 8];
            }
#pragma unroll
            for (int j = 0; j < 8; j++) {
                const int n = wn0 + j * 8 + g;
                bH[j][0] = *(const uint32_t*)&sBh[n * KS_STR + kk];
                bH[j][1] = *(const uint32_t*)&sBh[n * KS_STR + kk + 8];
                bL[j][0] = *(const uint32_t*)&sBl[n * KS_STR + kk];
                bL[j][1] = *(const uint32_t*)&sBl[n * KS_STR + kk + 8];
            }
#pragma unroll
            for (int i = 0; i < 2; i++)
#pragma unroll
                for (int j = 0; j < 8; j++) {
                    mma_bf16(acc[i][j], aH[i], bH[j]);
                    mma_bf16(acc[i][j], aH[i], bL[j]);
                    mma_bf16(acc[i][j], aL[i], bH[j]);
                }
        }
        __syncthreads();
    }

    // epilogue: scatter to [B,H,L,64] with bias
#pragma unroll
    for (int i = 0; i < 2; i++) {
#pragma unroll
        for (int j = 0; j < 8; j++) {
            const int cc = n0 + wn0 + j * 8 + t4 * 2;
            const int hh = cc >> 6;
            const int dh = cc & 63;
            const float b0 = __ldg(&bias[cc]);
            const float b1 = __ldg(&bias[cc + 1]);
#pragma unroll
            for (int rr = 0; rr < 2; rr++) {
                const int r = m0 + wm0 + i * 16 + g + rr * 8;
                const int bidx = r / L;
                const int l    = r - bidx * L;
                float2 v;
                v.x = acc[i][j][rr * 2 + 0] + b0;
                v.y = acc[i][j][rr * 2 + 1] + b1;
                *(float2*)(out + ((size_t)(bidx * NH + hh) * L + l) * DHD + dh) = v;
            }
        }
    }
}

// =================================================================================
// Fused attention with relative_key_query position scores (flash-style, fp32).
// (unchanged from R1 — passes with rel_err 1.2e-6)
// =================================================================================
#define SMEM_FLOATS (4*64*65 + 127*65 + 64)
#define SMEM_BYTES  (SMEM_FLOATS * 4)

__global__ __launch_bounds__(256, 2)
void attn_kernel(const float* __restrict__ mask, const float* __restrict__ dist_emb,
                 float* __restrict__ out)
{
    extern __shared__ float sm[];
    float* Qs = sm;
    float* Ks = Qs + 64 * 65;
    float* Vs = Ks + 64 * 65;
    float* Ps = Vs + 64 * 65;
    float* Es = Ps + 64 * 65;
    float* Ms = Es + 127 * 65;

    const int t  = threadIdx.x;
    const int tx = t & 15;
    const int ty = t >> 4;
    const int qt = blockIdx.x;
    const int h  = blockIdx.y;
    const int b  = blockIdx.z;
    const int l0 = qt * 64;

    const float* Qg  = g_Q + ((size_t)(b * NH + h) * LQ + l0) * DHD;
    const float* Kg0 = g_K + (size_t)(b * NH + h) * LK * DHD;
    const float* Vg0 = g_V + (size_t)(b * NH + h) * LK * DHD;

    for (int g = t; g < 64 * 16; g += 256) {
        const int row = g >> 4, c4 = g & 15;
        float4 v = *(const float4*)(Qg + (size_t)row * 64 + c4 * 4);
        float* p = &Qs[row * 65 + c4 * 4];
        p[0] = v.x; p[1] = v.y; p[2] = v.z; p[3] = v.w;
    }

    float O[4][4];
    float mrow[4], lsum[4];
#pragma unroll
    for (int i = 0; i < 4; i++) {
        mrow[i] = -INFINITY; lsum[i] = 0.0f;
#pragma unroll
        for (int j = 0; j < 4; j++) O[i][j] = 0.0f;
    }

    int qb[4], kb[4], eb[7];
#pragma unroll
    for (int i = 0; i < 4; i++) qb[i] = (ty + 16 * i) * 65;
#pragma unroll
    for (int j = 0; j < 4; j++) kb[j] = (tx + 16 * j) * 65;
    const int dl0 = ty - tx + 15;
#pragma unroll
    for (int m = 0; m < 7; m++) eb[m] = (dl0 + 16 * m) * 65;

    for (int kt = 0; kt < LK / 64; kt++) {
        const int r0 = kt * 64;
        __syncthreads();

        for (int g = t; g < 64 * 16; g += 256) {
            const int row = g >> 4, c4 = g & 15;
            float4 kv = *(const float4*)(Kg0 + (size_t)(r0 + row) * 64 + c4 * 4);
            float* pk = &Ks[row * 65 + c4 * 4];
            pk[0] = kv.x; pk[1] = kv.y; pk[2] = kv.z; pk[3] = kv.w;
            float4 vv = *(const float4*)(Vg0 + (size_t)(r0 + row) * 64 + c4 * 4);
            float* pv = &Vs[row * 65 + c4 * 4];
            pv[0] = vv.x; pv[1] = vv.y; pv[2] = vv.z; pv[3] = vv.w;
        }
        const int idx_base = l0 - r0 + (MAXPOS - 64);
        for (int g = t; g < 127 * 16; g += 256) {
            const int row = g >> 4, c4 = g & 15;
            float4 ev = *(const float4*)(dist_emb + (size_t)(idx_base + row) * 64 + c4 * 4);
            float* pe = &Es[row * 65 + c4 * 4];
            pe[0] = ev.x; pe[1] = ev.y; pe[2] = ev.z; pe[3] = ev.w;
        }
        if (t < 64) Ms[t] = mask[(size_t)b * LK + r0 + t];
        __syncthreads();

        float s[4][4];
#pragma unroll
        for (int i = 0; i < 4; i++)
#pragma unroll
            for (int j = 0; j < 4; j++) s[i][j] = 0.0f;

#pragma unroll 4
        for (int d = 0; d < 64; d++) {
            float a[4], kv[4], e[7];
#pragma unroll
            for (int i = 0; i < 4; i++) a[i]  = Qs[qb[i] + d];
#pragma unroll
            for (int j = 0; j < 4; j++) kv[j] = Ks[kb[j] + d];
#pragma unroll
            for (int m = 0; m < 7; m++) e[m]  = Es[eb[m] + d];
#pragma unroll
            for (int i = 0; i < 4; i++)
#pragma unroll
                for (int j = 0; j < 4; j++) {
                    s[i][j] = fmaf(a[i], kv[j], s[i][j]);
                    s[i][j] = fmaf(a[i] + kv[j], e[i - j + 3], s[i][j]);
                }
        }

#pragma unroll
        for (int i = 0; i < 4; i++) {
            float sv[4];
            float rmax = -INFINITY;
#pragma unroll
            for (int j = 0; j < 4; j++) {
                sv[j] = s[i][j] * 0.125f + Ms[tx + 16 * j];
                rmax  = fmaxf(rmax, sv[j]);
            }
#pragma unroll
            for (int off = 1; off < 16; off <<= 1)
                rmax = fmaxf(rmax, __shfl_xor_sync(0xffffffffu, rmax, off));
            const float mnew = fmaxf(mrow[i], rmax);
            const float corr = __expf(mrow[i] - mnew);
            float rs = 0.0f;
#pragma unroll
            for (int j = 0; j < 4; j++) {
                const float p = __expf(sv[j] - mnew);
                s[i][j] = p;
                rs += p;
            }
#pragma unroll
            for (int off = 1; off < 16; off <<= 1)
                rs += __shfl_xor_sync(0xffffffffu, rs, off);
            lsum[i] = lsum[i] * corr + rs;
#pragma unroll
            for (int j = 0; j < 4; j++) O[i][j] *= corr;
            mrow[i] = mnew;
        }

#pragma unroll
        for (int i = 0; i < 4; i++)
#pragma unroll
            for (int j = 0; j < 4; j++)
                Ps[qb[i] + tx + 16 * j] = s[i][j];
        __syncthreads();

#pragma unroll 4
        for (int r = 0; r < 64; r++) {
            float pr[4], vv[4];
#pragma unroll
            for (int i = 0; i < 4; i++) pr[i] = Ps[qb[i] + r];
#pragma unroll
            for (int j = 0; j < 4; j++) vv[j] = Vs[r * 65 + tx + 16 * j];
#pragma unroll
            for (int i = 0; i < 4; i++)
#pragma unroll
                for (int j = 0; j < 4; j++)
                    O[i][j] = fmaf(pr[i], vv[j], O[i][j]);
        }
    }

#pragma unroll
    for (int i = 0; i < 4; i++) {
        const int l = l0 + ty + 16 * i;
        const float inv = 1.0f / lsum[i];
        float* op = out + ((size_t)b * LQ + l) * DM + h * 64;
#pragma unroll
        for (int j = 0; j < 4; j++)
            op[tx + 16 * j] = O[i][j] * inv;
    }
}

// =================================================================================
extern "C" void kernel_launch(void* const* d_in, const int* in_sizes, int n_in,
                              void* d_out, int out_size)
{
    const float* hidden   = (const float*)d_in[0];
    const float* q_hidden = (const float*)d_in[1];
    const float* mask     = (const float*)d_in[2];
    const float* Wq       = (const float*)d_in[3];
    const float* bq       = (const float*)d_in[4];
    const float* Wk       = (const float*)d_in[5];
    const float* bk       = (const float*)d_in[6];
    const float* Wv       = (const float*)d_in[7];
    const float* bv       = (const float*)d_in[8];
    const float* dist     = (const float*)d_in[9];
    float* out = (float*)d_out;

    float *Qp, *Kp, *Vp;
    cudaGetSymbolAddress((void**)&Qp, g_Q);
    cudaGetSymbolAddress((void**)&Kp, g_K);
    cudaGetSymbolAddress((void**)&Vp, g_V);
    __nv_bfloat16 *Xqh, *Xql, *Xkh, *Xkl, *Wh, *Wl;
    cudaGetSymbolAddress((void**)&Xqh, g_Xqh);
    cudaGetSymbolAddress((void**)&Xql, g_Xql);
    cudaGetSymbolAddress((void**)&Xkh, g_Xkh);
    cudaGetSymbolAddress((void**)&Xkl, g_Xkl);
    cudaGetSymbolAddress((void**)&Wh, g_Wh);
    cudaGetSymbolAddress((void**)&Wl, g_Wl);

    cudaFuncSetAttribute(attn_kernel, cudaFuncAttributeMaxDynamicSharedMemorySize,
                         SMEM_BYTES);
    cudaFuncSetAttribute(proj_tc, cudaFuncAttributeMaxDynamicSharedMemorySize,
                         PROJ_SMEM_BYTES);

    // fp32 -> bf16 hi/lo splits
    const int nq  = NB * LQ * DM / 4;
    const int nk  = NB * LK * DM / 4;
    const int nw  = DM * DM / 4;
    split_kernel<<<(nq + 255) / 256, 256>>>(q_hidden, Xqh, Xql, nq);
    split_kernel<<<(nk + 255) / 256, 256>>>(hidden,   Xkh, Xkl, nk);
    split_kernel<<<(nw + 255) / 256, 256>>>(Wq, Wh + 0 * (size_t)DM * DM, Wl + 0 * (size_t)DM * DM, nw);
    split_kernel<<<(nw + 255) / 256, 256>>>(Wk, Wh + 1 * (size_t)DM * DM, Wl + 1 * (size_t)DM * DM, nw);
    split_kernel<<<(nw + 255) / 256, 256>>>(Wv, Wh + 2 * (size_t)DM * DM, Wl + 2 * (size_t)DM * DM, nw);

    // tensor-core projections (mma.sync bf16 split)
    dim3 gq(NB * LQ / 128, DM / 128);   // 32 x 8
    dim3 gk(NB * LK / 128, DM / 128);   // 64 x 8
    proj_tc<<<gq, 256, PROJ_SMEM_BYTES>>>(Xqh, Xql,
        Wh + 0 * (size_t)DM * DM, Wl + 0 * (size_t)DM * DM, bq, Qp, LQ);
    proj_tc<<<gk, 256, PROJ_SMEM_BYTES>>>(Xkh, Xkl,
        Wh + 1 * (size_t)DM * DM, Wl + 1 * (size_t)DM * DM, bk, Kp, LK);
    proj_tc<<<gk, 256, PROJ_SMEM_BYTES>>>(Xkh, Xkl,
        Wh + 2 * (size_t)DM * DM, Wl + 2 * (size_t)DM * DM, bv, Vp, LK);

    // attention
    dim3 ga(LQ / 64, NH, NB);
    attn_kernel<<<ga, 256, SMEM_BYTES>>>(mask, dist, out);
}